// round 8
// baseline (speedup 1.0000x reference)
#include <cuda_runtime.h>
#include <math.h>

#define BB 64
#define NN 4096
#define KS 16
#define DI 256
#define DO 256
#define HI 512
#define TT 3
#define LN_EPS 1e-5f
#define NCH 32   // n-chunks for the big attention pass (128 rows per block)
#define SCH 32   // chunks for the LN0 stats pass

// packed fp32x2 FMA (Blackwell FFMA2 — only reachable via PTX)
__device__ __forceinline__ void ffma2(float2& d, float2 a, float2 b) {
    asm("fma.rn.f32x2 %0, %1, %2, %0;"
        : "+l"(reinterpret_cast<unsigned long long&>(d))
        : "l"(reinterpret_cast<unsigned long long&>(a)),
          "l"(reinterpret_cast<unsigned long long&>(b)));
}

// ---------------- device scratch (static, no allocations) ----------------
__device__ float g_spartA[SCH * BB];
__device__ float g_spartB[SCH * BB];
__device__ float g_mean[BB];
__device__ float g_rstd[BB];
__device__ float g_slots[BB * KS * DO];
__device__ float g_qk[BB * KS * DI];     // PRE-scaled by 1/KS
__device__ float g_qkb[BB * KS];         // PRE-scaled by 1/KS
__device__ float g_upart[(size_t)NCH * BB * KS * DI];
__device__ float g_Spart[NCH * BB * KS];
__device__ float g_spre[BB * KS * DO];
// folded / transposed weights (per-iteration buffers, filled up front)
__device__ float g_Wqk[TT * DO * DI];
__device__ float g_wqb[TT * DI];
__device__ float g_wb[TT * DO];
__device__ float g_c0[TT];
__device__ float g_vWt[TT * DI * DO];
__device__ float g_m1Wt[TT * DO * HI];
__device__ float g_m2Wt[TT * HI * DO];

// ---------------- generic 32x32 tiled transpose -------------------------
__global__ void __launch_bounds__(256) k_tr(const float* __restrict__ src,
                                            float* __restrict__ dst, int R, int C) {
    __shared__ float tile[32][33];
    int z = blockIdx.z;
    const float* s = src + (size_t)z * R * C;
    float* d = dst + (size_t)z * R * C;
    int c0 = blockIdx.x * 32, r0 = blockIdx.y * 32;
    int x = threadIdx.x & 31, y = threadIdx.x >> 5;
    for (int yy = y; yy < 32; yy += 8)
        tile[yy][x] = s[(size_t)(r0 + yy) * C + c0 + x];
    __syncthreads();
    for (int yy = y; yy < 32; yy += 8)
        d[(size_t)(c0 + yy) * R + r0 + x] = tile[x][yy];
}

// ---------------- LN0 statistics ----------------------------------------
__global__ void __launch_bounds__(256) k_stats(const float* __restrict__ in) {
    int b = blockIdx.x, c = blockIdx.y, tid = threadIdx.x;
    const float4* p = (const float4*)(in + (size_t)b * NN * DI);
    const int per = (NN * DI / 4) / SCH;
    float s = 0.f, s2 = 0.f;
    for (int i = tid; i < per; i += 256) {
        float4 v = p[(size_t)c * per + i];
        s  += v.x + v.y + v.z + v.w;
        s2 += v.x * v.x + v.y * v.y + v.z * v.z + v.w * v.w;
    }
    __shared__ float r1[256], r2[256];
    r1[tid] = s; r2[tid] = s2; __syncthreads();
    for (int o = 128; o > 0; o >>= 1) {
        if (tid < o) { r1[tid] += r1[tid + o]; r2[tid] += r2[tid + o]; }
        __syncthreads();
    }
    if (tid == 0) { g_spartA[c * BB + b] = r1[0]; g_spartB[c * BB + b] = r2[0]; }
}

__global__ void k_fin() {
    int b = threadIdx.x;
    if (b >= BB) return;
    float s = 0.f, s2 = 0.f;
    for (int c = 0; c < SCH; c++) { s += g_spartA[c * BB + b]; s2 += g_spartB[c * BB + b]; }
    const float inv = 1.0f / (float)(NN * DI);
    float m = s * inv;
    float v = s2 * inv - m * m;
    g_mean[b] = m;
    g_rstd[b] = rsqrtf(v + LN_EPS);
}

// ---------------- slots = mu + exp(logsigma) * slots_init ---------------
__global__ void k_sinit(const float* __restrict__ si, const float* __restrict__ mu,
                        const float* __restrict__ ls) {
    int i = blockIdx.x * 256 + threadIdx.x;
    int d = i & (DO - 1);
    g_slots[i] = mu[d] + expf(ls[d]) * si[i];
}

// ---------------- Wqk = qW^T @ kW  (grid: 64 x TT) ----------------------
__global__ void __launch_bounds__(256) k_wqk(const float* __restrict__ qW,
                                             const float* __restrict__ qb,
                                             const float* __restrict__ kW,
                                             const float* __restrict__ kb) {
    int d0 = blockIdx.x * 4, t = blockIdx.y, i = threadIdx.x;
    int wid = i >> 5, lane = i & 31;
    __shared__ float qcols[DO * 4];
    __shared__ float kb_s[DO], qb_s[DO];
    {
        float4 v = *(const float4*)(qW + (size_t)t * DO * DO + (size_t)i * DO + d0);
        qcols[i * 4 + 0] = v.x; qcols[i * 4 + 1] = v.y;
        qcols[i * 4 + 2] = v.z; qcols[i * 4 + 3] = v.w;
        kb_s[i] = kb[t * DO + i];
        qb_s[i] = qb[t * DO + i];
    }
    __syncthreads();
    const float* kWt = kW + (size_t)t * DO * DI;
    float acc0 = 0.f, acc1 = 0.f, acc2 = 0.f, acc3 = 0.f, accq = 0.f;
    for (int e = 0; e < DO; e++) {
        float kv = kWt[(size_t)e * DI + i];
        acc0 += qcols[e * 4 + 0] * kv;
        acc1 += qcols[e * 4 + 1] * kv;
        acc2 += qcols[e * 4 + 2] * kv;
        acc3 += qcols[e * 4 + 3] * kv;
        accq += qb_s[e] * kv;
    }
    float* Wq = g_Wqk + (size_t)t * DO * DI;
    Wq[(d0 + 0) * DI + i] = acc0;
    Wq[(d0 + 1) * DI + i] = acc1;
    Wq[(d0 + 2) * DI + i] = acc2;
    Wq[(d0 + 3) * DI + i] = acc3;
    if (blockIdx.x == 0) g_wqb[t * DI + i] = accq;
    if (wid < 4) {
        float s = 0.f;
        for (int e = lane; e < DO; e += 32) s += qcols[e * 4 + wid] * kb_s[e];
#pragma unroll
        for (int o = 16; o > 0; o >>= 1) s += __shfl_xor_sync(0xffffffffu, s, o);
        if (lane == 0) g_wb[t * DO + d0 + wid] = s;
    }
    if (blockIdx.x == 0 && wid == 4) {
        float s = 0.f;
        for (int e = lane; e < DO; e += 32) s += qb_s[e] * kb_s[e];
#pragma unroll
        for (int o = 16; o > 0; o >>= 1) s += __shfl_xor_sync(0xffffffffu, s, o);
        if (lane == 0) g_c0[t] = s;
    }
}

// ---------------- LN1(slots) -> qk = sn @ Wqk + wqb  (grid: BB x 2) -----
__global__ void __launch_bounds__(256) k_qk(const float* __restrict__ ln1w,
                                            const float* __restrict__ ln1b, int t) {
    int b = blockIdx.x, kh = blockIdx.y, tid = threadIdx.x;
    int wid = tid >> 5, lane = tid & 31;
    __shared__ float sl[KS * DO];
    __shared__ float ss[8 * DO];
    __shared__ float r1[256], r2[256];
    float s = 0.f, s2 = 0.f;
    for (int i = tid; i < KS * DO; i += 256) {
        float v = g_slots[b * KS * DO + i];
        sl[i] = v; s += v; s2 += v * v;
    }
    r1[tid] = s; r2[tid] = s2; __syncthreads();
    for (int o = 128; o > 0; o >>= 1) {
        if (tid < o) { r1[tid] += r1[tid + o]; r2[tid] += r2[tid + o]; }
        __syncthreads();
    }
    const float invC = 1.0f / (float)(KS * DO);
    float m = r1[0] * invC;
    float rs = rsqrtf(r2[0] * invC - m * m + LN_EPS);
    for (int i = tid; i < 8 * DO; i += 256) {
        int gi = kh * 8 * DO + i;
        ss[i] = (sl[gi] - m) * rs * ln1w[gi] + ln1b[gi];
    }
    __syncthreads();

    const float isc = 1.0f / (float)KS;
    const float* Wq = g_Wqk + (size_t)t * DO * DI;
    float acc[8] = {0.f, 0.f, 0.f, 0.f, 0.f, 0.f, 0.f, 0.f};
    for (int d = 0; d < DO; d++) {
        float wv = Wq[d * DI + tid];
#pragma unroll
        for (int k = 0; k < 8; k++) acc[k] += ss[k * DO + d] * wv;
    }
    float wqbv = g_wqb[t * DI + tid];
#pragma unroll
    for (int k = 0; k < 8; k++)
        g_qk[b * KS * DI + (kh * 8 + k) * DI + tid] = (acc[k] + wqbv) * isc;
    {
        float sb = 0.f;
        const float* wb = g_wb + t * DO;
        for (int d = lane; d < DO; d += 32) sb += ss[wid * DO + d] * wb[d];
#pragma unroll
        for (int o = 16; o > 0; o >>= 1) sb += __shfl_xor_sync(0xffffffffu, sb, o);
        if (lane == 0) g_qkb[b * KS + kh * 8 + wid] = (sb + g_c0[t]) * isc;
    }
}

// ---------------- big fused attention pass  (grid: BB x NCH) ------------
// Register-blocked: thread = (sp: slot pair, dgl/wq: 4 scattered float4
// columns covering 16 d, nh: 8-row n-half). Each LDS.128 feeds 4 ffma2.
#define XSTR 264   // row stride in floats (66 float4)
__global__ void __launch_bounds__(256, 2) k_attn(const float* __restrict__ in,
                                                 const float* __restrict__ ln0w,
                                                 const float* __restrict__ ln0b) {
    int b = blockIdx.x, ch = blockIdx.y, tid = threadIdx.x;
    int lane = tid & 31, w = tid >> 5;
    int sp = lane & 7, dgl = lane >> 3;      // slot pair, 0..3
    int wq = w & 3, nh = w >> 2;             // column block, n-half
    int k0 = 2 * sp, k1 = 2 * sp + 1;
    int fbase = dgl + wq * 4;                // float4 column base; +j*16

    __shared__ float4 xs4[16 * 66];          // 16 rows x 264 floats (aliased as merge buf)
    __shared__ float  attn[KS][17];
    __shared__ float  red[8][8][16];         // [warp][sp][slot*8 + n-local]
    __shared__ float  qkb_s[KS];
    float* xs = (float*)xs4;

    // q: 2 slots x 4 scattered float4 -> 16 float2 regs (already /KS scaled)
    const float4* qbase = (const float4*)(g_qk + (size_t)b * KS * DI);
    float2 q0[8], q1[8];
#pragma unroll
    for (int j = 0; j < 4; j++) {
        float4 a = qbase[k0 * 64 + fbase + j * 16];
        q0[2 * j]     = make_float2(a.x, a.y);
        q0[2 * j + 1] = make_float2(a.z, a.w);
        float4 c = qbase[k1 * 64 + fbase + j * 16];
        q1[2 * j]     = make_float2(c.x, c.y);
        q1[2 * j + 1] = make_float2(c.z, c.w);
    }
    if (tid < KS) qkb_s[tid] = g_qkb[b * KS + tid];
    float mean = g_mean[b], rstd = g_rstd[b];

    float2 u0[8], u1[8];
#pragma unroll
    for (int j = 0; j < 8; j++) { u0[j] = make_float2(0.f, 0.f); u1[j] = make_float2(0.f, 0.f); }
    float Sa = 0.f;
    __syncthreads();

    for (int g = 0; g < 8; g++) {
        int n0 = ch * 128 + g * 16;
        const float4* xin = (const float4*)(in + ((size_t)b * NN + n0) * DI);
        const float4* wv4 = (const float4*)(ln0w + (size_t)n0 * DI);
        const float4* bv4 = (const float4*)(ln0b + (size_t)n0 * DI);
        for (int i = tid; i < 1024; i += 256) {
            int row = i >> 6, c = i & 63;
            float4 v = xin[i], ww = wv4[i], bb = bv4[i];
            float4 o;
            o.x = (v.x - mean) * rstd * ww.x + bb.x;
            o.y = (v.y - mean) * rstd * ww.y + bb.y;
            o.z = (v.z - mean) * rstd * ww.z + bb.z;
            o.w = (v.w - mean) * rstd * ww.w + bb.w;
            xs4[row * 66 + c] = o;
        }
        __syncthreads();

        // phase1: 2 slots x 8 n partial dots over 16 scattered d
        float p0[8], p1[8];
#pragma unroll
        for (int n = 0; n < 8; n++) {
            const float4* xr = (const float4*)(xs + (nh * 8 + n) * XSTR) + fbase;
            float2 a0 = make_float2(0.f, 0.f), a1 = make_float2(0.f, 0.f);
#pragma unroll
            for (int j = 0; j < 4; j++) {
                float4 xv = xr[j * 16];
                float2 lo = make_float2(xv.x, xv.y), hi = make_float2(xv.z, xv.w);
                ffma2(a0, q0[2 * j], lo); ffma2(a0, q0[2 * j + 1], hi);
                ffma2(a1, q1[2 * j], lo); ffma2(a1, q1[2 * j + 1], hi);
            }
            p0[n] = a0.x + a0.y; p1[n] = a1.x + a1.y;
        }
        // reduce over the 4 dgl lanes (bits 3,4 of lane)
#pragma unroll
        for (int n = 0; n < 8; n++) {
            p0[n] += __shfl_xor_sync(0xffffffffu, p0[n], 8);
            p0[n] += __shfl_xor_sync(0xffffffffu, p0[n], 16);
            p1[n] += __shfl_xor_sync(0xffffffffu, p1[n], 8);
            p1[n] += __shfl_xor_sync(0xffffffffu, p1[n], 16);
        }
        if (dgl == 0) {
#pragma unroll
            for (int n = 0; n < 8; n++) { red[w][sp][n] = p0[n]; red[w][sp][8 + n] = p1[n]; }
        }
        __syncthreads();

        // softmax over slot dim (32 lanes; assembles dist from red inline)
        if (tid < 32) {
            int n = lane & 15, h = lane >> 4;
            int nhh = n >> 3, nl = n & 7;
            float dv[8];
#pragma unroll
            for (int jj = 0; jj < 8; jj++) {
                int kk = h * 8 + jj;
                int spp = kk >> 1, ssl = kk & 1;
                float sum = 0.f;
#pragma unroll
                for (int q = 0; q < 4; q++) sum += red[nhh * 4 + q][spp][ssl * 8 + nl];
                dv[jj] = sum + qkb_s[kk];
            }
            float mx = -1e30f;
#pragma unroll
            for (int jj = 0; jj < 8; jj++) mx = fmaxf(mx, dv[jj]);
            mx = fmaxf(mx, __shfl_xor_sync(0xffffffffu, mx, 16));
            float e[8]; float sm = 0.f;
#pragma unroll
            for (int jj = 0; jj < 8; jj++) { e[jj] = __expf(dv[jj] - mx); sm += e[jj]; }
            sm += __shfl_xor_sync(0xffffffffu, sm, 16);
            float iv = 1.0f / sm;
#pragma unroll
            for (int jj = 0; jj < 8; jj++) attn[h * 8 + jj][n] = e[jj] * iv;
        }
        __syncthreads();

        if (tid < 16) {
#pragma unroll
            for (int n = 0; n < 16; n++) Sa += attn[tid][n];
        }

        // phase2: u[2 slots][16 scattered d] over this thread's 8 n
#pragma unroll
        for (int n = 0; n < 8; n++) {
            int rn = nh * 8 + n;
            float wa0 = attn[k0][rn], wa1 = attn[k1][rn];
            float2 w0 = make_float2(wa0, wa0), w1 = make_float2(wa1, wa1);
            const float4* xr = (const float4*)(xs + rn * XSTR) + fbase;
#pragma unroll
            for (int j = 0; j < 4; j++) {
                float4 xv = xr[j * 16];
                float2 lo = make_float2(xv.x, xv.y), hi = make_float2(xv.z, xv.w);
                ffma2(u0[2 * j], w0, lo); ffma2(u0[2 * j + 1], w0, hi);
                ffma2(u1[2 * j], w1, lo); ffma2(u1[2 * j + 1], w1, hi);
            }
        }
        __syncthreads();
    }

    // merge nh halves in smem (xs dead), then coalesced store
    float* us = xs;   // [16 slots][256 floats]
    if (nh == 1) {
#pragma unroll
        for (int j = 0; j < 4; j++) {
            int fcol = (fbase + j * 16) * 4;
            *(float4*)&us[k0 * 256 + fcol] =
                make_float4(u0[2 * j].x, u0[2 * j].y, u0[2 * j + 1].x, u0[2 * j + 1].y);
            *(float4*)&us[k1 * 256 + fcol] =
                make_float4(u1[2 * j].x, u1[2 * j].y, u1[2 * j + 1].x, u1[2 * j + 1].y);
        }
    }
    __syncthreads();
    if (nh == 0) {
#pragma unroll
        for (int j = 0; j < 4; j++) {
            int fcol = (fbase + j * 16) * 4;
            float4 a = *(float4*)&us[k0 * 256 + fcol];
            a.x += u0[2 * j].x; a.y += u0[2 * j].y; a.z += u0[2 * j + 1].x; a.w += u0[2 * j + 1].y;
            *(float4*)&us[k0 * 256 + fcol] = a;
            float4 c = *(float4*)&us[k1 * 256 + fcol];
            c.x += u1[2 * j].x; c.y += u1[2 * j].y; c.z += u1[2 * j + 1].x; c.w += u1[2 * j + 1].y;
            *(float4*)&us[k1 * 256 + fcol] = c;
        }
    }
    __syncthreads();
    float4* up = (float4*)(g_upart + (((size_t)ch * BB + b) * KS) * DI);
    for (int i = tid; i < 1024; i += 256) up[i] = ((float4*)us)[i];
    if (tid < 16) g_Spart[(ch * BB + b) * KS + tid] = Sa;
}

// ---------------- reduce partials, V proj  (grid: BB x 2) ---------------
__global__ void __launch_bounds__(256) k_vproj(const float* __restrict__ vb, int t) {
    int b = blockIdx.x, kh = blockIdx.y, tid = threadIdx.x;
    __shared__ float wxs[8 * DI];
    __shared__ float wss[8], ivs[8];
    if (tid < 8) {
        float S = 0.f;
        for (int c = 0; c < NCH; c++) S += g_Spart[(c * BB + b) * KS + kh * 8 + tid];
        float iv = 1.0f / (S + 1e-7f);
        ivs[tid] = iv; wss[tid] = S * iv;
    }
    __syncthreads();
    for (int ii = tid; ii < 512; ii += 256) {
        int k = ii >> 6;
        const float4* src = (const float4*)g_upart +
            (((size_t)b * KS) + kh * 8 + k) * (DI / 4) + (ii & 63);
        float4 s = make_float4(0.f, 0.f, 0.f, 0.f);
#pragma unroll 8
        for (int c = 0; c < NCH; c++) {
            float4 v = src[(size_t)c * (BB * KS * DI / 4)];
            s.x += v.x; s.y += v.y; s.z += v.z; s.w += v.w;
        }
        float iv = ivs[k];
        s.x *= iv; s.y *= iv; s.z *= iv; s.w *= iv;
        ((float4*)wxs)[ii] = s;
    }
    __syncthreads();
    const float* vt = g_vWt + (size_t)t * DI * DO;
    float acc[8] = {0.f, 0.f, 0.f, 0.f, 0.f, 0.f, 0.f, 0.f};
    for (int d = 0; d < DI; d++) {
        float wv = vt[(size_t)d * DO + tid];
#pragma unroll
        for (int k = 0; k < 8; k++) acc[k] += wxs[k * DI + d] * wv;
    }
    float vbv = vb[t * DO + tid];
#pragma unroll
    for (int k = 0; k < 8; k++)
        g_spre[b * KS * DO + (kh * 8 + k) * DO + tid] = acc[k] + vbv * wss[k];
}

// ---------------- LN2 + MLP + residual ----------------------------------
__global__ void __launch_bounds__(256) k_mlp(const float* __restrict__ ln2w,
                                             const float* __restrict__ ln2b,
                                             const float* __restrict__ m1b,
                                             const float* __restrict__ m2b,
                                             int t, float* __restrict__ out) {
    int b = blockIdx.x, kq = blockIdx.y, tid = threadIdx.x;
    __shared__ float h0[4 * DO];
    __shared__ float hh[4 * HI];
    __shared__ float r1[256], r2[256];
    float s = 0.f, s2 = 0.f;
    for (int i = tid; i < KS * DO; i += 256) {
        float v = g_spre[b * KS * DO + i];
        s += v; s2 += v * v;
    }
    r1[tid] = s; r2[tid] = s2; __syncthreads();
    for (int o = 128; o > 0; o >>= 1) {
        if (tid < o) { r1[tid] += r1[tid + o]; r2[tid] += r2[tid + o]; }
        __syncthreads();
    }
    const float invC = 1.0f / (float)(KS * DO);
    float m = r1[0] * invC;
    float rs = rsqrtf(r2[0] * invC - m * m + LN_EPS);
    for (int i = tid; i < 4 * DO; i += 256) {
        int gi = kq * 4 * DO + i;
        float v = g_spre[b * KS * DO + gi];
        h0[i] = (v - m) * rs * ln2w[gi] + ln2b[gi];
    }
    __syncthreads();

    const float* w1 = g_m1Wt + (size_t)t * DO * HI;
    {
        float a0[4] = {0.f, 0.f, 0.f, 0.f}, a1[4] = {0.f, 0.f, 0.f, 0.f};
        for (int d = 0; d < DO; d++) {
            float wA = w1[(size_t)d * HI + tid];
            float wB = w1[(size_t)d * HI + tid + 256];
#pragma unroll
            for (int k = 0; k < 4; k++) {
                float hv = h0[k * DO + d];
                a0[k] += hv * wA; a1[k] += hv * wB;
            }
        }
        float bA = m1b[t * HI + tid], bB = m1b[t * HI + tid + 256];
#pragma unroll
        for (int k = 0; k < 4; k++) {
            hh[k * HI + tid]       = fmaxf(a0[k] + bA, 0.f);
            hh[k * HI + tid + 256] = fmaxf(a1[k] + bB, 0.f);
        }
    }
    __syncthreads();

    const float* w2 = g_m2Wt + (size_t)t * HI * DO;
    float a[4] = {0.f, 0.f, 0.f, 0.f};
    for (int h = 0; h < HI; h++) {
        float wv = w2[(size_t)h * DO + tid];
#pragma unroll
        for (int k = 0; k < 4; k++) a[k] += hh[k * HI + h] * wv;
    }
    float b2 = m2b[t * DO + tid];
#pragma unroll
    for (int k = 0; k < 4; k++) {
        int gi = (kq * 4 + k) * DO + tid;
        float val = g_spre[b * KS * DO + gi] + a[k] + b2;
        g_slots[b * KS * DO + gi] = val;
        if (out) out[(size_t)b * KS * DO + gi] = val;
    }
}

// ---------------- host launcher -----------------------------------------
extern "C" void kernel_launch(void* const* d_in, const int* in_sizes, int n_in,
                              void* d_out, int out_size) {
    const float* inputs     = (const float*)d_in[0];
    const float* slots_init = (const float*)d_in[1];
    const float* mu         = (const float*)d_in[2];
    const float* logsigma   = (const float*)d_in[3];
    const float* ln0w       = (const float*)d_in[4];
    const float* ln0b       = (const float*)d_in[5];
    const float* ln1w       = (const float*)d_in[6];
    const float* ln1b       = (const float*)d_in[7];
    const float* ln2w       = (const float*)d_in[8];
    const float* ln2b       = (const float*)d_in[9];
    const float* qW         = (const float*)d_in[10];
    const float* qb         = (const float*)d_in[11];
    const float* kW         = (const float*)d_in[12];
    const float* kb         = (const float*)d_in[13];
    const float* vW         = (const float*)d_in[14];
    const float* vb         = (const float*)d_in[15];
    const float* m1W        = (const float*)d_in[16];
    const float* m1b        = (const float*)d_in[17];
    const float* m2W        = (const float*)d_in[18];
    const float* m2b        = (const float*)d_in[19];
    float* out = (float*)d_out;

    float* vWt;  cudaGetSymbolAddress((void**)&vWt,  g_vWt);
    float* m1Wt; cudaGetSymbolAddress((void**)&m1Wt, g_m1Wt);
    float* m2Wt; cudaGetSymbolAddress((void**)&m2Wt, g_m2Wt);
    k_tr<<<dim3(DI / 32, DO / 32, TT), 256>>>(vW, vWt, DO, DI);
    k_tr<<<dim3(DO / 32, HI / 32, TT), 256>>>(m1W, m1Wt, HI, DO);
    k_tr<<<dim3(HI / 32, DO / 32, TT), 256>>>(m2W, m2Wt, DO, HI);

    k_wqk<<<dim3(64, TT), 256>>>(qW, qb, kW, kb);   // all iterations up front
    k_stats<<<dim3(BB, SCH), 256>>>(inputs);
    k_fin<<<1, BB>>>();
    k_sinit<<<(BB * KS * DO) / 256, 256>>>(slots_init, mu, logsigma);

    for (int t = 0; t < TT; t++) {
        k_qk<<<dim3(BB, 2), 256>>>(ln1w, ln1b, t);
        k_attn<<<dim3(BB, NCH), 256>>>(inputs, ln0w, ln0b);
        k_vproj<<<dim3(BB, 2), 256>>>(vb, t);
        k_mlp<<<dim3(BB, 4), 256>>>(ln2w, ln2b, m1b, m2b, t,
                                    (t == TT - 1) ? out : (float*)nullptr);
    }
}

// round 9
// speedup vs baseline: 1.5344x; 1.5344x over previous
#include <cuda_runtime.h>
#include <math.h>

#define BB 64
#define NN 4096
#define KS 16
#define DI 256
#define DO 256
#define HI 512
#define TT 3
#define LN_EPS 1e-5f
#define NCH 32   // n-chunks for the big attention pass (128 rows per block)
#define SCH 32   // chunks for streaming passes

// packed fp32x2 FMA (Blackwell FFMA2 — only reachable via PTX)
__device__ __forceinline__ void ffma2(float2& d, float2 a, float2 b) {
    asm("fma.rn.f32x2 %0, %1, %2, %0;"
        : "+l"(reinterpret_cast<unsigned long long&>(d))
        : "l"(reinterpret_cast<unsigned long long&>(a)),
          "l"(reinterpret_cast<unsigned long long&>(b)));
}

// cp.async helpers (LDGSTS)
__device__ __forceinline__ void cpasync16(void* smem, const void* gmem) {
    unsigned a = (unsigned)__cvta_generic_to_shared(smem);
    asm volatile("cp.async.cg.shared.global [%0], [%1], 16;" :: "r"(a), "l"(gmem));
}
__device__ __forceinline__ void cp_commit() {
    asm volatile("cp.async.commit_group;");
}
template <int N>
__device__ __forceinline__ void cp_wait() {
    asm volatile("cp.async.wait_group %0;" :: "n"(N));
}

// ---------------- device scratch (static, no allocations) ----------------
__device__ float g_spartA[SCH * BB];
__device__ float g_spartB[SCH * BB];
__device__ float g_mean[BB];
__device__ float g_rstd[BB];
__device__ float g_xn[(size_t)BB * NN * DI];   // LN0(x), 268 MB
__device__ float g_slots[BB * KS * DO];
__device__ float g_qk[BB * KS * DI];     // PRE-scaled by 1/KS
__device__ float g_qkb[BB * KS];         // PRE-scaled by 1/KS
__device__ float g_upart[(size_t)NCH * BB * KS * DI];
__device__ float g_Spart[NCH * BB * KS];
__device__ float g_spre[BB * KS * DO];
// folded / transposed weights (per-iteration buffers, filled up front)
__device__ float g_Wqk[TT * DO * DI];
__device__ float g_wqb[TT * DI];
__device__ float g_wb[TT * DO];
__device__ float g_c0[TT];
__device__ float g_vWt[TT * DI * DO];
__device__ float g_m1Wt[TT * DO * HI];
__device__ float g_m2Wt[TT * HI * DO];

// ---------------- generic 32x32 tiled transpose -------------------------
__global__ void __launch_bounds__(256) k_tr(const float* __restrict__ src,
                                            float* __restrict__ dst, int R, int C) {
    __shared__ float tile[32][33];
    int z = blockIdx.z;
    const float* s = src + (size_t)z * R * C;
    float* d = dst + (size_t)z * R * C;
    int c0 = blockIdx.x * 32, r0 = blockIdx.y * 32;
    int x = threadIdx.x & 31, y = threadIdx.x >> 5;
    for (int yy = y; yy < 32; yy += 8)
        tile[yy][x] = s[(size_t)(r0 + yy) * C + c0 + x];
    __syncthreads();
    for (int yy = y; yy < 32; yy += 8)
        d[(size_t)(c0 + yy) * R + r0 + x] = tile[x][yy];
}

// ---------------- LN0 statistics ----------------------------------------
__global__ void __launch_bounds__(256) k_stats(const float* __restrict__ in) {
    int b = blockIdx.x, c = blockIdx.y, tid = threadIdx.x;
    const float4* p = (const float4*)(in + (size_t)b * NN * DI);
    const int per = (NN * DI / 4) / SCH;
    float s = 0.f, s2 = 0.f;
    for (int i = tid; i < per; i += 256) {
        float4 v = p[(size_t)c * per + i];
        s  += v.x + v.y + v.z + v.w;
        s2 += v.x * v.x + v.y * v.y + v.z * v.z + v.w * v.w;
    }
    __shared__ float r1[256], r2[256];
    r1[tid] = s; r2[tid] = s2; __syncthreads();
    for (int o = 128; o > 0; o >>= 1) {
        if (tid < o) { r1[tid] += r1[tid + o]; r2[tid] += r2[tid + o]; }
        __syncthreads();
    }
    if (tid == 0) { g_spartA[c * BB + b] = r1[0]; g_spartB[c * BB + b] = r2[0]; }
}

__global__ void k_fin() {
    int b = threadIdx.x;
    if (b >= BB) return;
    float s = 0.f, s2 = 0.f;
    for (int c = 0; c < SCH; c++) { s += g_spartA[c * BB + b]; s2 += g_spartB[c * BB + b]; }
    const float inv = 1.0f / (float)(NN * DI);
    float m = s * inv;
    float v = s2 * inv - m * m;
    g_mean[b] = m;
    g_rstd[b] = rsqrtf(v + LN_EPS);
}

// ---------------- x_hat = LN0(x) materialized once ----------------------
__global__ void __launch_bounds__(256) k_ln0(const float* __restrict__ in,
                                             const float* __restrict__ w,
                                             const float* __restrict__ bb) {
    int b = blockIdx.x, c = blockIdx.y, tid = threadIdx.x;
    const int per = (NN * DI / 4) / SCH;   // 8192 float4
    float mean = g_mean[b], rstd = g_rstd[b];
    const float4* xin = (const float4*)(in + (size_t)b * NN * DI) + (size_t)c * per;
    const float4* w4  = (const float4*)w  + (size_t)c * per;
    const float4* b4  = (const float4*)bb + (size_t)c * per;
    float4* xo = (float4*)(g_xn + (size_t)b * NN * DI) + (size_t)c * per;
    for (int i = tid; i < per; i += 256) {
        float4 v = xin[i], ww = w4[i], bv = b4[i], o;
        o.x = (v.x - mean) * rstd * ww.x + bv.x;
        o.y = (v.y - mean) * rstd * ww.y + bv.y;
        o.z = (v.z - mean) * rstd * ww.z + bv.z;
        o.w = (v.w - mean) * rstd * ww.w + bv.w;
        xo[i] = o;
    }
}

// ---------------- slots = mu + exp(logsigma) * slots_init ---------------
__global__ void k_sinit(const float* __restrict__ si, const float* __restrict__ mu,
                        const float* __restrict__ ls) {
    int i = blockIdx.x * 256 + threadIdx.x;
    int d = i & (DO - 1);
    g_slots[i] = mu[d] + expf(ls[d]) * si[i];
}

// ---------------- Wqk = qW^T @ kW  (grid: 64 x TT) ----------------------
__global__ void __launch_bounds__(256) k_wqk(const float* __restrict__ qW,
                                             const float* __restrict__ qb,
                                             const float* __restrict__ kW,
                                             const float* __restrict__ kb) {
    int d0 = blockIdx.x * 4, t = blockIdx.y, i = threadIdx.x;
    int wid = i >> 5, lane = i & 31;
    __shared__ float qcols[DO * 4];
    __shared__ float kb_s[DO], qb_s[DO];
    {
        float4 v = *(const float4*)(qW + (size_t)t * DO * DO + (size_t)i * DO + d0);
        qcols[i * 4 + 0] = v.x; qcols[i * 4 + 1] = v.y;
        qcols[i * 4 + 2] = v.z; qcols[i * 4 + 3] = v.w;
        kb_s[i] = kb[t * DO + i];
        qb_s[i] = qb[t * DO + i];
    }
    __syncthreads();
    const float* kWt = kW + (size_t)t * DO * DI;
    float acc0 = 0.f, acc1 = 0.f, acc2 = 0.f, acc3 = 0.f, accq = 0.f;
    for (int e = 0; e < DO; e++) {
        float kv = kWt[(size_t)e * DI + i];
        acc0 += qcols[e * 4 + 0] * kv;
        acc1 += qcols[e * 4 + 1] * kv;
        acc2 += qcols[e * 4 + 2] * kv;
        acc3 += qcols[e * 4 + 3] * kv;
        accq += qb_s[e] * kv;
    }
    float* Wq = g_Wqk + (size_t)t * DO * DI;
    Wq[(d0 + 0) * DI + i] = acc0;
    Wq[(d0 + 1) * DI + i] = acc1;
    Wq[(d0 + 2) * DI + i] = acc2;
    Wq[(d0 + 3) * DI + i] = acc3;
    if (blockIdx.x == 0) g_wqb[t * DI + i] = accq;
    if (wid < 4) {
        float s = 0.f;
        for (int e = lane; e < DO; e += 32) s += qcols[e * 4 + wid] * kb_s[e];
#pragma unroll
        for (int o = 16; o > 0; o >>= 1) s += __shfl_xor_sync(0xffffffffu, s, o);
        if (lane == 0) g_wb[t * DO + d0 + wid] = s;
    }
    if (blockIdx.x == 0 && wid == 4) {
        float s = 0.f;
        for (int e = lane; e < DO; e += 32) s += qb_s[e] * kb_s[e];
#pragma unroll
        for (int o = 16; o > 0; o >>= 1) s += __shfl_xor_sync(0xffffffffu, s, o);
        if (lane == 0) g_c0[t] = s;
    }
}

// ---------------- LN1(slots) -> qk = sn @ Wqk + wqb  (grid: BB x 2) -----
__global__ void __launch_bounds__(256) k_qk(const float* __restrict__ ln1w,
                                            const float* __restrict__ ln1b, int t) {
    int b = blockIdx.x, kh = blockIdx.y, tid = threadIdx.x;
    int wid = tid >> 5, lane = tid & 31;
    __shared__ float sl[KS * DO];
    __shared__ float ss[8 * DO];
    __shared__ float r1[256], r2[256];
    float s = 0.f, s2 = 0.f;
    for (int i = tid; i < KS * DO; i += 256) {
        float v = g_slots[b * KS * DO + i];
        sl[i] = v; s += v; s2 += v * v;
    }
    r1[tid] = s; r2[tid] = s2; __syncthreads();
    for (int o = 128; o > 0; o >>= 1) {
        if (tid < o) { r1[tid] += r1[tid + o]; r2[tid] += r2[tid + o]; }
        __syncthreads();
    }
    const float invC = 1.0f / (float)(KS * DO);
    float m = r1[0] * invC;
    float rs = rsqrtf(r2[0] * invC - m * m + LN_EPS);
    for (int i = tid; i < 8 * DO; i += 256) {
        int gi = kh * 8 * DO + i;
        ss[i] = (sl[gi] - m) * rs * ln1w[gi] + ln1b[gi];
    }
    __syncthreads();

    const float isc = 1.0f / (float)KS;
    const float* Wq = g_Wqk + (size_t)t * DO * DI;
    float acc[8] = {0.f, 0.f, 0.f, 0.f, 0.f, 0.f, 0.f, 0.f};
    for (int d = 0; d < DO; d++) {
        float wv = Wq[d * DI + tid];
#pragma unroll
        for (int k = 0; k < 8; k++) acc[k] += ss[k * DO + d] * wv;
    }
    float wqbv = g_wqb[t * DI + tid];
#pragma unroll
    for (int k = 0; k < 8; k++)
        g_qk[b * KS * DI + (kh * 8 + k) * DI + tid] = (acc[k] + wqbv) * isc;
    {
        float sb = 0.f;
        const float* wb = g_wb + t * DO;
        for (int d = lane; d < DO; d += 32) sb += ss[wid * DO + d] * wb[d];
#pragma unroll
        for (int o = 16; o > 0; o >>= 1) sb += __shfl_xor_sync(0xffffffffu, sb, o);
        if (lane == 0) g_qkb[b * KS + kh * 8 + wid] = (sb + g_c0[t]) * isc;
    }
}

// ---------------- big fused attention pass  (grid: BB x NCH) ------------
// R6 thread mapping (kk = tid&15, dg = tid>>4) + precomputed x_hat +
// cp.async double-buffered staging (16 KB per tile, prefetch overlaps compute).
__global__ void __launch_bounds__(256, 2) k_attn() {
    int b = blockIdx.x, ch = blockIdx.y, tid = threadIdx.x;
    int kk = tid & 15, dg = tid >> 4;
    int wid = tid >> 5, lane = tid & 31;

    __shared__ float4 xs[2][16 * 65];    // double-buffered tiles, 33 KB
    __shared__ float  dist[KS][17];
    __shared__ float  attn[KS][17];
    __shared__ float  red[8][16 * 17];
    __shared__ float  qkb_s[KS];

    // qk segment for (kk, dg): 16 floats as 8 float2 (already /KS scaled)
    const float2* qp = (const float2*)(g_qk + ((size_t)b * KS + kk) * DI + dg * 16);
    float2 q[8];
#pragma unroll
    for (int j = 0; j < 8; j++) q[j] = qp[j];
    if (tid < KS) qkb_s[tid] = g_qkb[b * KS + tid];

    float2 u[8];
#pragma unroll
    for (int j = 0; j < 8; j++) u[j] = make_float2(0.f, 0.f);
    float Sa = 0.f;

    const float4* xnb = (const float4*)(g_xn + ((size_t)b * NN + (size_t)ch * 128) * DI);

    // prefetch tile 0
#pragma unroll
    for (int k = 0; k < 4; k++) {
        int i = tid + k * 256;
        cpasync16(&xs[0][(i >> 6) * 65 + (i & 63)], &xnb[i]);
    }
    cp_commit();

    for (int g = 0; g < 8; g++) {
        const float4* buf = xs[g & 1];
        if (g < 7) {
            float4* nb = xs[(g + 1) & 1];
            const float4* src = xnb + (size_t)(g + 1) * 1024;
#pragma unroll
            for (int k = 0; k < 4; k++) {
                int i = tid + k * 256;
                cpasync16(&nb[(i >> 6) * 65 + (i & 63)], &src[i]);
            }
            cp_commit();
            cp_wait<1>();
        } else {
            cp_wait<0>();
        }
        __syncthreads();

        // phase1: packed partial dots over this thread's 16-d segment
        float p[16];
#pragma unroll
        for (int n = 0; n < 16; n++) {
            const float2* xr = (const float2*)&buf[n * 65 + dg * 4];
            float2 acc = make_float2(0.f, 0.f);
#pragma unroll
            for (int j = 0; j < 8; j++) ffma2(acc, q[j], xr[j]);
            p[n] = acc.x + acc.y;
        }
#pragma unroll
        for (int n = 0; n < 16; n++)
            p[n] += __shfl_xor_sync(0xffffffffu, p[n], 16);
        if (lane < 16) {
#pragma unroll
            for (int n = 0; n < 16; n++) red[wid][lane * 17 + n] = p[n];
        }
        __syncthreads();

        // reduce 8 warps -> dist
        {
            int rkk = tid & 15, rn = tid >> 4;
            float s = 0.f;
#pragma unroll
            for (int w = 0; w < 8; w++) s += red[w][rkk * 17 + rn];
            dist[rkk][rn] = s + qkb_s[rkk];
        }
        __syncthreads();

        // softmax over slot dim: 32 lanes, n = lane&15, k-half = lane>>4
        if (tid < 32) {
            int n = lane & 15, h = lane >> 4;
            float mx = -1e30f;
#pragma unroll
            for (int j = 0; j < 8; j++) mx = fmaxf(mx, dist[h * 8 + j][n]);
            mx = fmaxf(mx, __shfl_xor_sync(0xffffffffu, mx, 16));
            float e[8]; float sm = 0.f;
#pragma unroll
            for (int j = 0; j < 8; j++) {
                e[j] = __expf(dist[h * 8 + j][n] - mx);
                sm += e[j];
            }
            sm += __shfl_xor_sync(0xffffffffu, sm, 16);
            float iv = 1.0f / sm;
#pragma unroll
            for (int j = 0; j < 8; j++) attn[h * 8 + j][n] = e[j] * iv;
        }
        __syncthreads();

        if (tid < 16) {
#pragma unroll
            for (int n = 0; n < 16; n++) Sa += attn[tid][n];
        }

        // phase2: packed u accumulation (x reads are 2-address broadcasts)
#pragma unroll
        for (int n = 0; n < 16; n++) {
            float w = attn[kk][n];
            float2 w2 = make_float2(w, w);
            const float2* xr = (const float2*)&buf[n * 65 + dg * 4];
#pragma unroll
            for (int j = 0; j < 8; j++) ffma2(u[j], w2, xr[j]);
        }
        __syncthreads();   // all reads of buf done -> safe to prefetch into it
    }

    float4* up = (float4*)(g_upart + (((size_t)ch * BB + b) * KS + kk) * DI + dg * 16);
    up[0] = make_float4(u[0].x, u[0].y, u[1].x, u[1].y);
    up[1] = make_float4(u[2].x, u[2].y, u[3].x, u[3].y);
    up[2] = make_float4(u[4].x, u[4].y, u[5].x, u[5].y);
    up[3] = make_float4(u[6].x, u[6].y, u[7].x, u[7].y);
    if (tid < 16) g_Spart[(ch * BB + b) * KS + tid] = Sa;
}

// ---------------- reduce partials, V proj  (grid: BB x 2) ---------------
__global__ void __launch_bounds__(256) k_vproj(const float* __restrict__ vb, int t) {
    int b = blockIdx.x, kh = blockIdx.y, tid = threadIdx.x;
    __shared__ float wxs[8 * DI];
    __shared__ float wss[8], ivs[8];
    if (tid < 8) {
        float S = 0.f;
        for (int c = 0; c < NCH; c++) S += g_Spart[(c * BB + b) * KS + kh * 8 + tid];
        float iv = 1.0f / (S + 1e-7f);
        ivs[tid] = iv; wss[tid] = S * iv;
    }
    __syncthreads();
    for (int ii = tid; ii < 512; ii += 256) {
        int k = ii >> 6;
        const float4* src = (const float4*)g_upart +
            (((size_t)b * KS) + kh * 8 + k) * (DI / 4) + (ii & 63);
        float4 s = make_float4(0.f, 0.f, 0.f, 0.f);
#pragma unroll 8
        for (int c = 0; c < NCH; c++) {
            float4 v = src[(size_t)c * (BB * KS * DI / 4)];
            s.x += v.x; s.y += v.y; s.z += v.z; s.w += v.w;
        }
        float iv = ivs[k];
        s.x *= iv; s.y *= iv; s.z *= iv; s.w *= iv;
        ((float4*)wxs)[ii] = s;
    }
    __syncthreads();
    const float* vt = g_vWt + (size_t)t * DI * DO;
    float acc[8] = {0.f, 0.f, 0.f, 0.f, 0.f, 0.f, 0.f, 0.f};
    for (int d = 0; d < DI; d++) {
        float wv = vt[(size_t)d * DO + tid];
#pragma unroll
        for (int k = 0; k < 8; k++) acc[k] += wxs[k * DI + d] * wv;
    }
    float vbv = vb[t * DO + tid];
#pragma unroll
    for (int k = 0; k < 8; k++)
        g_spre[b * KS * DO + (kh * 8 + k) * DO + tid] = acc[k] + vbv * wss[k];
}

// ---------------- LN2 + MLP + residual ----------------------------------
__global__ void __launch_bounds__(256) k_mlp(const float* __restrict__ ln2w,
                                             const float* __restrict__ ln2b,
                                             const float* __restrict__ m1b,
                                             const float* __restrict__ m2b,
                                             int t, float* __restrict__ out) {
    int b = blockIdx.x, kq = blockIdx.y, tid = threadIdx.x;
    __shared__ float h0[4 * DO];
    __shared__ float hh[4 * HI];
    __shared__ float r1[256], r2[256];
    float s = 0.f, s2 = 0.f;
    for (int i = tid; i < KS * DO; i += 256) {
        float v = g_spre[b * KS * DO + i];
        s += v; s2 += v * v;
    }
    r1[tid] = s; r2[tid] = s2; __syncthreads();
    for (int o = 128; o > 0; o >>= 1) {
        if (tid < o) { r1[tid] += r1[tid + o]; r2[tid] += r2[tid + o]; }
        __syncthreads();
    }
    const float invC = 1.0f / (float)(KS * DO);
    float m = r1[0] * invC;
    float rs = rsqrtf(r2[0] * invC - m * m + LN_EPS);
    for (int i = tid; i < 4 * DO; i += 256) {
        int gi = kq * 4 * DO + i;
        float v = g_spre[b * KS * DO + gi];
        h0[i] = (v - m) * rs * ln2w[gi] + ln2b[gi];
    }
    __syncthreads();

    const float* w1 = g_m1Wt + (size_t)t * DO * HI;
    {
        float a0[4] = {0.f, 0.f, 0.f, 0.f}, a1[4] = {0.f, 0.f, 0.f, 0.f};
        for (int d = 0; d < DO; d++) {
            float wA = w1[(size_t)d * HI + tid];
            float wB = w1[(size_t)d * HI + tid + 256];
#pragma unroll
            for (int k = 0; k < 4; k++) {
                float hv = h0[k * DO + d];
                a0[k] += hv * wA; a1[k] += hv * wB;
            }
        }
        float bA = m1b[t * HI + tid], bB = m1b[t * HI + tid + 256];
#pragma unroll
        for (int k = 0; k < 4; k++) {
            hh[k * HI + tid]       = fmaxf(a0[k] + bA, 0.f);
            hh[k * HI + tid + 256] = fmaxf(a1[k] + bB, 0.f);
        }
    }
    __syncthreads();

    const float* w2 = g_m2Wt + (size_t)t * HI * DO;
    float a[4] = {0.f, 0.f, 0.f, 0.f};
    for (int h = 0; h < HI; h++) {
        float wv = w2[(size_t)h * DO + tid];
#pragma unroll
        for (int k = 0; k < 4; k++) a[k] += hh[k * HI + h] * wv;
    }
    float b2 = m2b[t * DO + tid];
#pragma unroll
    for (int k = 0; k < 4; k++) {
        int gi = (kq * 4 + k) * DO + tid;
        float val = g_spre[b * KS * DO + gi] + a[k] + b2;
        g_slots[b * KS * DO + gi] = val;
        if (out) out[(size_t)b * KS * DO + gi] = val;
    }
}

// ---------------- host launcher -----------------------------------------
extern "C" void kernel_launch(void* const* d_in, const int* in_sizes, int n_in,
                              void* d_out, int out_size) {
    const float* inputs     = (const float*)d_in[0];
    const float* slots_init = (const float*)d_in[1];
    const float* mu         = (const float*)d_in[2];
    const float* logsigma   = (const float*)d_in[3];
    const float* ln0w       = (const float*)d_in[4];
    const float* ln0b       = (const float*)d_in[5];
    const float* ln1w       = (const float*)d_in[6];
    const float* ln1b       = (const float*)d_in[7];
    const float* ln2w       = (const float*)d_in[8];
    const float* ln2b       = (const float*)d_in[9];
    const float* qW         = (const float*)d_in[10];
    const float* qb         = (const float*)d_in[11];
    const float* kW         = (const float*)d_in[12];
    const float* kb         = (const float*)d_in[13];
    const float* vW         = (const float*)d_in[14];
    const float* vb         = (const float*)d_in[15];
    const float* m1W        = (const float*)d_in[16];
    const float* m1b        = (const float*)d_in[17];
    const float* m2W        = (const float*)d_in[18];
    const float* m2b        = (const float*)d_in[19];
    float* out = (float*)d_out;

    float* vWt;  cudaGetSymbolAddress((void**)&vWt,  g_vWt);
    float* m1Wt; cudaGetSymbolAddress((void**)&m1Wt, g_m1Wt);
    float* m2Wt; cudaGetSymbolAddress((void**)&m2Wt, g_m2Wt);
    k_tr<<<dim3(DI / 32, DO / 32, TT), 256>>>(vW, vWt, DO, DI);
    k_tr<<<dim3(DO / 32, HI / 32, TT), 256>>>(m1W, m1Wt, HI, DO);
    k_tr<<<dim3(HI / 32, DO / 32, TT), 256>>>(m2W, m2Wt, DO, HI);

    k_wqk<<<dim3(64, TT), 256>>>(qW, qb, kW, kb);   // all iterations up front
    k_stats<<<dim3(BB, SCH), 256>>>(inputs);
    k_fin<<<1, BB>>>();
    k_ln0<<<dim3(BB, SCH), 256>>>(inputs, ln0w, ln0b);
    k_sinit<<<(BB * KS * DO) / 256, 256>>>(slots_init, mu, logsigma);

    for (int t = 0; t < TT; t++) {
        k_qk<<<dim3(BB, 2), 256>>>(ln1w, ln1b, t);
        k_attn<<<dim3(BB, NCH), 256>>>();
        k_vproj<<<dim3(BB, 2), 256>>>(vb, t);
        k_mlp<<<dim3(BB, 4), 256>>>(ln2w, ln2b, m1b, m2b, t,
                                    (t == TT - 1) ? out : (float*)nullptr);
    }
}

// round 10
// speedup vs baseline: 1.5543x; 1.0130x over previous
#include <cuda_runtime.h>
#include <math.h>

#define BB 64
#define NN 4096
#define KS 16
#define DI 256
#define DO 256
#define HI 512
#define TT 3
#define LN_EPS 1e-5f
#define NCH 32   // n-chunks for the big attention pass (128 rows per block)
#define SCH 32   // chunks for streaming passes

// packed fp32x2 FMA (Blackwell FFMA2 — only reachable via PTX)
__device__ __forceinline__ void ffma2(float2& d, float2 a, float2 b) {
    asm("fma.rn.f32x2 %0, %1, %2, %0;"
        : "+l"(reinterpret_cast<unsigned long long&>(d))
        : "l"(reinterpret_cast<unsigned long long&>(a)),
          "l"(reinterpret_cast<unsigned long long&>(b)));
}

// cp.async helpers (LDGSTS)
__device__ __forceinline__ void cpasync16(void* smem, const void* gmem) {
    unsigned a = (unsigned)__cvta_generic_to_shared(smem);
    asm volatile("cp.async.cg.shared.global [%0], [%1], 16;" :: "r"(a), "l"(gmem));
}
__device__ __forceinline__ void cp_commit() {
    asm volatile("cp.async.commit_group;");
}
template <int N>
__device__ __forceinline__ void cp_wait() {
    asm volatile("cp.async.wait_group %0;" :: "n"(N));
}

// ---------------- device scratch (static, no allocations) ----------------
__device__ float g_spartA[SCH * BB];
__device__ float g_spartB[SCH * BB];
__device__ float g_mean[BB];
__device__ float g_rstd[BB];
__device__ float g_xn[(size_t)BB * NN * DI];   // LN0(x), 268 MB
__device__ float g_slots[BB * KS * DO];
__device__ float g_qk[BB * KS * DI];     // PRE-scaled by 1/KS
__device__ float g_qkb[BB * KS];         // PRE-scaled by 1/KS
__device__ float g_upart[(size_t)NCH * BB * KS * DI];
__device__ float g_Spart[NCH * BB * KS];
__device__ float g_spre[BB * KS * DO];
// folded / transposed weights (per-iteration buffers, filled up front)
__device__ float g_Wqk[TT * DO * DI];
__device__ float g_wqb[TT * DI];
__device__ float g_wb[TT * DO];
__device__ float g_c0[TT];
__device__ float g_vWt[TT * DI * DO];
__device__ float g_m1Wt[TT * DO * HI];
__device__ float g_m2Wt[TT * HI * DO];

// ---------------- generic 32x32 tiled transpose -------------------------
__global__ void __launch_bounds__(256) k_tr(const float* __restrict__ src,
                                            float* __restrict__ dst, int R, int C) {
    __shared__ float tile[32][33];
    int z = blockIdx.z;
    const float* s = src + (size_t)z * R * C;
    float* d = dst + (size_t)z * R * C;
    int c0 = blockIdx.x * 32, r0 = blockIdx.y * 32;
    int x = threadIdx.x & 31, y = threadIdx.x >> 5;
    for (int yy = y; yy < 32; yy += 8)
        tile[yy][x] = s[(size_t)(r0 + yy) * C + c0 + x];
    __syncthreads();
    for (int yy = y; yy < 32; yy += 8)
        d[(size_t)(c0 + yy) * R + r0 + x] = tile[x][yy];
}

// ---------------- LN0 statistics ----------------------------------------
__global__ void __launch_bounds__(256) k_stats(const float* __restrict__ in) {
    int b = blockIdx.x, c = blockIdx.y, tid = threadIdx.x;
    const float4* p = (const float4*)(in + (size_t)b * NN * DI);
    const int per = (NN * DI / 4) / SCH;
    float s = 0.f, s2 = 0.f;
    for (int i = tid; i < per; i += 256) {
        float4 v = p[(size_t)c * per + i];
        s  += v.x + v.y + v.z + v.w;
        s2 += v.x * v.x + v.y * v.y + v.z * v.z + v.w * v.w;
    }
    __shared__ float r1[256], r2[256];
    r1[tid] = s; r2[tid] = s2; __syncthreads();
    for (int o = 128; o > 0; o >>= 1) {
        if (tid < o) { r1[tid] += r1[tid + o]; r2[tid] += r2[tid + o]; }
        __syncthreads();
    }
    if (tid == 0) { g_spartA[c * BB + b] = r1[0]; g_spartB[c * BB + b] = r2[0]; }
}

__global__ void k_fin() {
    int b = threadIdx.x;
    if (b >= BB) return;
    float s = 0.f, s2 = 0.f;
    for (int c = 0; c < SCH; c++) { s += g_spartA[c * BB + b]; s2 += g_spartB[c * BB + b]; }
    const float inv = 1.0f / (float)(NN * DI);
    float m = s * inv;
    float v = s2 * inv - m * m;
    g_mean[b] = m;
    g_rstd[b] = rsqrtf(v + LN_EPS);
}

// ---------------- x_hat = LN0(x) materialized once ----------------------
__global__ void __launch_bounds__(256) k_ln0(const float* __restrict__ in,
                                             const float* __restrict__ w,
                                             const float* __restrict__ bb) {
    int b = blockIdx.x, c = blockIdx.y, tid = threadIdx.x;
    const int per = (NN * DI / 4) / SCH;   // 8192 float4
    float mean = g_mean[b], rstd = g_rstd[b];
    const float4* xin = (const float4*)(in + (size_t)b * NN * DI) + (size_t)c * per;
    const float4* w4  = (const float4*)w  + (size_t)c * per;
    const float4* b4  = (const float4*)bb + (size_t)c * per;
    float4* xo = (float4*)(g_xn + (size_t)b * NN * DI) + (size_t)c * per;
    for (int i = tid; i < per; i += 256) {
        float4 v = xin[i], ww = w4[i], bv = b4[i], o;
        o.x = (v.x - mean) * rstd * ww.x + bv.x;
        o.y = (v.y - mean) * rstd * ww.y + bv.y;
        o.z = (v.z - mean) * rstd * ww.z + bv.z;
        o.w = (v.w - mean) * rstd * ww.w + bv.w;
        xo[i] = o;
    }
}

// ---------------- slots = mu + exp(logsigma) * slots_init ---------------
__global__ void k_sinit(const float* __restrict__ si, const float* __restrict__ mu,
                        const float* __restrict__ ls) {
    int i = blockIdx.x * 256 + threadIdx.x;
    int d = i & (DO - 1);
    g_slots[i] = mu[d] + expf(ls[d]) * si[i];
}

// ---------------- Wqk = qW^T @ kW  (grid: 64 x TT) ----------------------
__global__ void __launch_bounds__(256) k_wqk(const float* __restrict__ qW,
                                             const float* __restrict__ qb,
                                             const float* __restrict__ kW,
                                             const float* __restrict__ kb) {
    int d0 = blockIdx.x * 4, t = blockIdx.y, i = threadIdx.x;
    int wid = i >> 5, lane = i & 31;
    __shared__ float qcols[DO * 4];
    __shared__ float kb_s[DO], qb_s[DO];
    {
        float4 v = *(const float4*)(qW + (size_t)t * DO * DO + (size_t)i * DO + d0);
        qcols[i * 4 + 0] = v.x; qcols[i * 4 + 1] = v.y;
        qcols[i * 4 + 2] = v.z; qcols[i * 4 + 3] = v.w;
        kb_s[i] = kb[t * DO + i];
        qb_s[i] = qb[t * DO + i];
    }
    __syncthreads();
    const float* kWt = kW + (size_t)t * DO * DI;
    float acc0 = 0.f, acc1 = 0.f, acc2 = 0.f, acc3 = 0.f, accq = 0.f;
    for (int e = 0; e < DO; e++) {
        float kv = kWt[(size_t)e * DI + i];
        acc0 += qcols[e * 4 + 0] * kv;
        acc1 += qcols[e * 4 + 1] * kv;
        acc2 += qcols[e * 4 + 2] * kv;
        acc3 += qcols[e * 4 + 3] * kv;
        accq += qb_s[e] * kv;
    }
    float* Wq = g_Wqk + (size_t)t * DO * DI;
    Wq[(d0 + 0) * DI + i] = acc0;
    Wq[(d0 + 1) * DI + i] = acc1;
    Wq[(d0 + 2) * DI + i] = acc2;
    Wq[(d0 + 3) * DI + i] = acc3;
    if (blockIdx.x == 0) g_wqb[t * DI + i] = accq;
    if (wid < 4) {
        float s = 0.f;
        for (int e = lane; e < DO; e += 32) s += qcols[e * 4 + wid] * kb_s[e];
#pragma unroll
        for (int o = 16; o > 0; o >>= 1) s += __shfl_xor_sync(0xffffffffu, s, o);
        if (lane == 0) g_wb[t * DO + d0 + wid] = s;
    }
    if (blockIdx.x == 0 && wid == 4) {
        float s = 0.f;
        for (int e = lane; e < DO; e += 32) s += qb_s[e] * kb_s[e];
#pragma unroll
        for (int o = 16; o > 0; o >>= 1) s += __shfl_xor_sync(0xffffffffu, s, o);
        if (lane == 0) g_c0[t] = s;
    }
}

// ---------------- LN1(slots) -> qk = sn @ Wqk + wqb  (grid: BB x 2) -----
__global__ void __launch_bounds__(256) k_qk(const float* __restrict__ ln1w,
                                            const float* __restrict__ ln1b, int t) {
    int b = blockIdx.x, kh = blockIdx.y, tid = threadIdx.x;
    int wid = tid >> 5, lane = tid & 31;
    __shared__ float sl[KS * DO];
    __shared__ float ss[8 * DO];
    __shared__ float r1[256], r2[256];
    float s = 0.f, s2 = 0.f;
    for (int i = tid; i < KS * DO; i += 256) {
        float v = g_slots[b * KS * DO + i];
        sl[i] = v; s += v; s2 += v * v;
    }
    r1[tid] = s; r2[tid] = s2; __syncthreads();
    for (int o = 128; o > 0; o >>= 1) {
        if (tid < o) { r1[tid] += r1[tid + o]; r2[tid] += r2[tid + o]; }
        __syncthreads();
    }
    const float invC = 1.0f / (float)(KS * DO);
    float m = r1[0] * invC;
    float rs = rsqrtf(r2[0] * invC - m * m + LN_EPS);
    for (int i = tid; i < 8 * DO; i += 256) {
        int gi = kh * 8 * DO + i;
        ss[i] = (sl[gi] - m) * rs * ln1w[gi] + ln1b[gi];
    }
    __syncthreads();

    const float isc = 1.0f / (float)KS;
    const float* Wq = g_Wqk + (size_t)t * DO * DI;
    float acc[8] = {0.f, 0.f, 0.f, 0.f, 0.f, 0.f, 0.f, 0.f};
    for (int d = 0; d < DO; d++) {
        float wv = Wq[d * DI + tid];
#pragma unroll
        for (int k = 0; k < 8; k++) acc[k] += ss[k * DO + d] * wv;
    }
    float wqbv = g_wqb[t * DI + tid];
#pragma unroll
    for (int k = 0; k < 8; k++)
        g_qk[b * KS * DI + (kh * 8 + k) * DI + tid] = (acc[k] + wqbv) * isc;
    {
        float sb = 0.f;
        const float* wb = g_wb + t * DO;
        for (int d = lane; d < DO; d += 32) sb += ss[wid * DO + d] * wb[d];
#pragma unroll
        for (int o = 16; o > 0; o >>= 1) sb += __shfl_xor_sync(0xffffffffu, sb, o);
        if (lane == 0) g_qkb[b * KS + kh * 8 + wid] = (sb + g_c0[t]) * isc;
    }
}

// ---------------- big fused attention pass  (grid: BB x NCH) ------------
// LDS.128 loads, fused parallel softmax, occ 3, cp.async double buffering.
__global__ void __launch_bounds__(256, 3) k_attn() {
    int b = blockIdx.x, ch = blockIdx.y, tid = threadIdx.x;
    int kk = tid & 15, dg = tid >> 4;
    int wid = tid >> 5, lane = tid & 31;

    __shared__ float4 xs[2][16 * 64];    // double-buffered tiles, 32 KB (no pad: reads broadcast)
    __shared__ float  attn[KS][17];
    __shared__ float  red[8][16 * 17];
    __shared__ float  qkb_s[KS];

    // qk segment for (kk, dg): 16 floats as 8 float2 (already /KS scaled)
    const float2* qp = (const float2*)(g_qk + ((size_t)b * KS + kk) * DI + dg * 16);
    float2 q[8];
#pragma unroll
    for (int j = 0; j < 8; j++) q[j] = qp[j];
    if (tid < KS) qkb_s[tid] = g_qkb[b * KS + tid];

    float2 u[8];
#pragma unroll
    for (int j = 0; j < 8; j++) u[j] = make_float2(0.f, 0.f);
    float Sa = 0.f;

    const float4* xnb = (const float4*)(g_xn + ((size_t)b * NN + (size_t)ch * 128) * DI);

    // prefetch tile 0 (linear layout, stride 64 float4)
#pragma unroll
    for (int k = 0; k < 4; k++) {
        int i = tid + k * 256;
        cpasync16(&xs[0][i], &xnb[i]);
    }
    cp_commit();

    for (int g = 0; g < 8; g++) {
        const float4* buf = xs[g & 1];
        if (g < 7) {
            float4* nb = xs[(g + 1) & 1];
            const float4* src = xnb + (size_t)(g + 1) * 1024;
#pragma unroll
            for (int k = 0; k < 4; k++) {
                int i = tid + k * 256;
                cpasync16(&nb[i], &src[i]);
            }
            cp_commit();
            cp_wait<1>();
        } else {
            cp_wait<0>();
        }
        __syncthreads();

        // phase1: float4 partial dots; immediate shfl-fold + store (no p[] array)
#pragma unroll
        for (int n = 0; n < 16; n++) {
            const float4* xr = &buf[n * 64 + dg * 4];
            float2 acc = make_float2(0.f, 0.f);
#pragma unroll
            for (int j = 0; j < 4; j++) {
                float4 xv = xr[j];
                ffma2(acc, q[2 * j],     make_float2(xv.x, xv.y));
                ffma2(acc, q[2 * j + 1], make_float2(xv.z, xv.w));
            }
            float p = acc.x + acc.y;
            p += __shfl_xor_sync(0xffffffffu, p, 16);   // fold dg pair
            if (lane < 16) red[wid][lane * 17 + n] = p;
        }
        __syncthreads();

        // fused dist-assembly + softmax: thread (rkk = tid&15, rn = tid>>4).
        // All 16 slots of one n sit in a 16-lane half-warp -> shfl reductions.
        {
            int rkk = tid & 15, rn = tid >> 4;
            float s = qkb_s[rkk];
#pragma unroll
            for (int w = 0; w < 8; w++) s += red[w][rkk * 17 + rn];
            float mx = s;
#pragma unroll
            for (int o = 1; o < 16; o <<= 1)
                mx = fmaxf(mx, __shfl_xor_sync(0xffffffffu, mx, o));
            float e = __expf(s - mx);
            float sm = e;
#pragma unroll
            for (int o = 1; o < 16; o <<= 1)
                sm += __shfl_xor_sync(0xffffffffu, sm, o);
            attn[rkk][rn] = e * (1.0f / sm);
        }
        __syncthreads();

        if (tid < 16) {
#pragma unroll
            for (int n = 0; n < 16; n++) Sa += attn[tid][n];
        }

        // phase2: float4 x loads (broadcast), packed u accumulation
#pragma unroll
        for (int n = 0; n < 16; n++) {
            float w = attn[kk][n];
            float2 w2 = make_float2(w, w);
            const float4* xr = &buf[n * 64 + dg * 4];
#pragma unroll
            for (int j = 0; j < 4; j++) {
                float4 xv = xr[j];
                ffma2(u[2 * j],     w2, make_float2(xv.x, xv.y));
                ffma2(u[2 * j + 1], w2, make_float2(xv.z, xv.w));
            }
        }
        __syncthreads();   // all reads of buf done -> safe to prefetch into it
    }

    float4* up = (float4*)(g_upart + (((size_t)ch * BB + b) * KS + kk) * DI + dg * 16);
    up[0] = make_float4(u[0].x, u[0].y, u[1].x, u[1].y);
    up[1] = make_float4(u[2].x, u[2].y, u[3].x, u[3].y);
    up[2] = make_float4(u[4].x, u[4].y, u[5].x, u[5].y);
    up[3] = make_float4(u[6].x, u[6].y, u[7].x, u[7].y);
    if (tid < 16) g_Spart[(ch * BB + b) * KS + tid] = Sa;
}

// ---------------- reduce partials, V proj  (grid: BB x 2) ---------------
__global__ void __launch_bounds__(256) k_vproj(const float* __restrict__ vb, int t) {
    int b = blockIdx.x, kh = blockIdx.y, tid = threadIdx.x;
    __shared__ float wxs[8 * DI];
    __shared__ float wss[8], ivs[8];
    if (tid < 8) {
        float S = 0.f;
        for (int c = 0; c < NCH; c++) S += g_Spart[(c * BB + b) * KS + kh * 8 + tid];
        float iv = 1.0f / (S + 1e-7f);
        ivs[tid] = iv; wss[tid] = S * iv;
    }
    __syncthreads();
    for (int ii = tid; ii < 512; ii += 256) {
        int k = ii >> 6;
        const float4* src = (const float4*)g_upart +
            (((size_t)b * KS) + kh * 8 + k) * (DI / 4) + (ii & 63);
        float4 s = make_float4(0.f, 0.f, 0.f, 0.f);
#pragma unroll 8
        for (int c = 0; c < NCH; c++) {
            float4 v = src[(size_t)c * (BB * KS * DI / 4)];
            s.x += v.x; s.y += v.y; s.z += v.z; s.w += v.w;
        }
        float iv = ivs[k];
        s.x *= iv; s.y *= iv; s.z *= iv; s.w *= iv;
        ((float4*)wxs)[ii] = s;
    }
    __syncthreads();
    const float* vt = g_vWt + (size_t)t * DI * DO;
    float acc[8] = {0.f, 0.f, 0.f, 0.f, 0.f, 0.f, 0.f, 0.f};
    for (int d = 0; d < DI; d++) {
        float wv = vt[(size_t)d * DO + tid];
#pragma unroll
        for (int k = 0; k < 8; k++) acc[k] += wxs[k * DI + d] * wv;
    }
    float vbv = vb[t * DO + tid];
#pragma unroll
    for (int k = 0; k < 8; k++)
        g_spre[b * KS * DO + (kh * 8 + k) * DO + tid] = acc[k] + vbv * wss[k];
}

// ---------------- LN2 + MLP + residual ----------------------------------
__global__ void __launch_bounds__(256) k_mlp(const float* __restrict__ ln2w,
                                             const float* __restrict__ ln2b,
                                             const float* __restrict__ m1b,
                                             const float* __restrict__ m2b,
                                             int t, float* __restrict__ out) {
    int b = blockIdx.x, kq = blockIdx.y, tid = threadIdx.x;
    __shared__ float h0[4 * DO];
    __shared__ float hh[4 * HI];
    __shared__ float r1[256], r2[256];
    float s = 0.f, s2 = 0.f;
    for (int i = tid; i < KS * DO; i += 256) {
        float v = g_spre[b * KS * DO + i];
        s += v; s2 += v * v;
    }
    r1[tid] = s; r2[tid] = s2; __syncthreads();
    for (int o = 128; o > 0; o >>= 1) {
        if (tid < o) { r1[tid] += r1[tid + o]; r2[tid] += r2[tid + o]; }
        __syncthreads();
    }
    const float invC = 1.0f / (float)(KS * DO);
    float m = r1[0] * invC;
    float rs = rsqrtf(r2[0] * invC - m * m + LN_EPS);
    for (int i = tid; i < 4 * DO; i += 256) {
        int gi = kq * 4 * DO + i;
        float v = g_spre[b * KS * DO + gi];
        h0[i] = (v - m) * rs * ln2w[gi] + ln2b[gi];
    }
    __syncthreads();

    const float* w1 = g_m1Wt + (size_t)t * DO * HI;
    {
        float a0[4] = {0.f, 0.f, 0.f, 0.f}, a1[4] = {0.f, 0.f, 0.f, 0.f};
        for (int d = 0; d < DO; d++) {
            float wA = w1[(size_t)d * HI + tid];
            float wB = w1[(size_t)d * HI + tid + 256];
#pragma unroll
            for (int k = 0; k < 4; k++) {
                float hv = h0[k * DO + d];
                a0[k] += hv * wA; a1[k] += hv * wB;
            }
        }
        float bA = m1b[t * HI + tid], bB = m1b[t * HI + tid + 256];
#pragma unroll
        for (int k = 0; k < 4; k++) {
            hh[k * HI + tid]       = fmaxf(a0[k] + bA, 0.f);
            hh[k * HI + tid + 256] = fmaxf(a1[k] + bB, 0.f);
        }
    }
    __syncthreads();

    const float* w2 = g_m2Wt + (size_t)t * HI * DO;
    float a[4] = {0.f, 0.f, 0.f, 0.f};
    for (int h = 0; h < HI; h++) {
        float wv = w2[(size_t)h * DO + tid];
#pragma unroll
        for (int k = 0; k < 4; k++) a[k] += hh[k * HI + h] * wv;
    }
    float b2 = m2b[t * DO + tid];
#pragma unroll
    for (int k = 0; k < 4; k++) {
        int gi = (kq * 4 + k) * DO + tid;
        float val = g_spre[b * KS * DO + gi] + a[k] + b2;
        g_slots[b * KS * DO + gi] = val;
        if (out) out[(size_t)b * KS * DO + gi] = val;
    }
}

// ---------------- host launcher -----------------------------------------
extern "C" void kernel_launch(void* const* d_in, const int* in_sizes, int n_in,
                              void* d_out, int out_size) {
    const float* inputs     = (const float*)d_in[0];
    const float* slots_init = (const float*)d_in[1];
    const float* mu         = (const float*)d_in[2];
    const float* logsigma   = (const float*)d_in[3];
    const float* ln0w       = (const float*)d_in[4];
    const float* ln0b       = (const float*)d_in[5];
    const float* ln1w       = (const float*)d_in[6];
    const float* ln1b       = (const float*)d_in[7];
    const float* ln2w       = (const float*)d_in[8];
    const float* ln2b       = (const float*)d_in[9];
    const float* qW         = (const float*)d_in[10];
    const float* qb         = (const float*)d_in[11];
    const float* kW         = (const float*)d_in[12];
    const float* kb         = (const float*)d_in[13];
    const float* vW         = (const float*)d_in[14];
    const float* vb         = (const float*)d_in[15];
    const float* m1W        = (const float*)d_in[16];
    const float* m1b        = (const float*)d_in[17];
    const float* m2W        = (const float*)d_in[18];
    const float* m2b        = (const float*)d_in[19];
    float* out = (float*)d_out;

    float* vWt;  cudaGetSymbolAddress((void**)&vWt,  g_vWt);
    float* m1Wt; cudaGetSymbolAddress((void**)&m1Wt, g_m1Wt);
    float* m2Wt; cudaGetSymbolAddress((void**)&m2Wt, g_m2Wt);
    k_tr<<<dim3(DI / 32, DO / 32, TT), 256>>>(vW, vWt, DO, DI);
    k_tr<<<dim3(DO / 32, HI / 32, TT), 256>>>(m1W, m1Wt, HI, DO);
    k_tr<<<dim3(HI / 32, DO / 32, TT), 256>>>(m2W, m2Wt, DO, HI);

    k_wqk<<<dim3(64, TT), 256>>>(qW, qb, kW, kb);   // all iterations up front
    k_stats<<<dim3(BB, SCH), 256>>>(inputs);
    k_fin<<<1, BB>>>();
    k_ln0<<<dim3(BB, SCH), 256>>>(inputs, ln0w, ln0b);
    k_sinit<<<(BB * KS * DO) / 256, 256>>>(slots_init, mu, logsigma);

    for (int t = 0; t < TT; t++) {
        k_qk<<<dim3(BB, 2), 256>>>(ln1w, ln1b, t);
        k_attn<<<dim3(BB, NCH), 256>>>();
        k_vproj<<<dim3(BB, 2), 256>>>(vb, t);
        k_mlp<<<dim3(BB, 4), 256>>>(ln2w, ln2b, m1b, m2b, t,
                                    (t == TT - 1) ? out : (float*)nullptr);
    }
}

// round 11
// speedup vs baseline: 1.6828x; 1.0826x over previous
#include <cuda_runtime.h>
#include <math.h>

#define BB 64
#define NN 4096
#define KS 16
#define DI 256
#define DO 256
#define HI 512
#define TT 3
#define LN_EPS 1e-5f
#define NCH 32   // n-chunks for the big attention pass (128 rows per block)
#define SCH 32   // chunks for streaming passes

// packed fp32x2 FMA (Blackwell FFMA2 — only reachable via PTX)
__device__ __forceinline__ void ffma2(float2& d, float2 a, float2 b) {
    asm("fma.rn.f32x2 %0, %1, %2, %0;"
        : "+l"(reinterpret_cast<unsigned long long&>(d))
        : "l"(reinterpret_cast<unsigned long long&>(a)),
          "l"(reinterpret_cast<unsigned long long&>(b)));
}

// cp.async helpers (LDGSTS)
__device__ __forceinline__ void cpasync16(void* smem, const void* gmem) {
    unsigned a = (unsigned)__cvta_generic_to_shared(smem);
    asm volatile("cp.async.cg.shared.global [%0], [%1], 16;" :: "r"(a), "l"(gmem));
}
__device__ __forceinline__ void cp_commit() {
    asm volatile("cp.async.commit_group;");
}
template <int N>
__device__ __forceinline__ void cp_wait() {
    asm volatile("cp.async.wait_group %0;" :: "n"(N));
}

// ---------------- device scratch (static, no allocations) ----------------
__device__ float g_spartA[SCH * BB];
__device__ float g_spartB[SCH * BB];
__device__ float g_mean[BB];
__device__ float g_rstd[BB];
__device__ float g_xn[(size_t)BB * NN * DI];   // LN0(x), 268 MB
__device__ float g_slots[BB * KS * DO];
__device__ float g_qk[BB * KS * DI];     // PRE-scaled by 1/KS
__device__ float g_qkb[BB * KS];         // PRE-scaled by 1/KS
__device__ float g_upart[(size_t)NCH * BB * KS * DI];
__device__ float g_Spart[NCH * BB * KS];
__device__ float g_spre[BB * KS * DO];
// folded / transposed weights (per-iteration buffers, filled up front)
__device__ float g_Wqk[TT * DO * DI];
__device__ float g_wqb[TT * DI];
__device__ float g_wb[TT * DO];
__device__ float g_c0[TT];
__device__ float g_vWt[TT * DI * DO];
__device__ float g_m1Wt[TT * DO * HI];
__device__ float g_m2Wt[TT * HI * DO];

// ---------------- generic 32x32 tiled transpose -------------------------
__global__ void __launch_bounds__(256) k_tr(const float* __restrict__ src,
                                            float* __restrict__ dst, int R, int C) {
    __shared__ float tile[32][33];
    int z = blockIdx.z;
    const float* s = src + (size_t)z * R * C;
    float* d = dst + (size_t)z * R * C;
    int c0 = blockIdx.x * 32, r0 = blockIdx.y * 32;
    int x = threadIdx.x & 31, y = threadIdx.x >> 5;
    for (int yy = y; yy < 32; yy += 8)
        tile[yy][x] = s[(size_t)(r0 + yy) * C + c0 + x];
    __syncthreads();
    for (int yy = y; yy < 32; yy += 8)
        d[(size_t)(c0 + yy) * R + r0 + x] = tile[x][yy];
}

// ---------------- LN0 statistics ----------------------------------------
__global__ void __launch_bounds__(256) k_stats(const float* __restrict__ in) {
    int b = blockIdx.x, c = blockIdx.y, tid = threadIdx.x;
    const float4* p = (const float4*)(in + (size_t)b * NN * DI);
    const int per = (NN * DI / 4) / SCH;
    float s = 0.f, s2 = 0.f;
    for (int i = tid; i < per; i += 256) {
        float4 v = p[(size_t)c * per + i];
        s  += v.x + v.y + v.z + v.w;
        s2 += v.x * v.x + v.y * v.y + v.z * v.z + v.w * v.w;
    }
    __shared__ float r1[256], r2[256];
    r1[tid] = s; r2[tid] = s2; __syncthreads();
    for (int o = 128; o > 0; o >>= 1) {
        if (tid < o) { r1[tid] += r1[tid + o]; r2[tid] += r2[tid + o]; }
        __syncthreads();
    }
    if (tid == 0) { g_spartA[c * BB + b] = r1[0]; g_spartB[c * BB + b] = r2[0]; }
}

__global__ void k_fin() {
    int b = threadIdx.x;
    if (b >= BB) return;
    float s = 0.f, s2 = 0.f;
    for (int c = 0; c < SCH; c++) { s += g_spartA[c * BB + b]; s2 += g_spartB[c * BB + b]; }
    const float inv = 1.0f / (float)(NN * DI);
    float m = s * inv;
    float v = s2 * inv - m * m;
    g_mean[b] = m;
    g_rstd[b] = rsqrtf(v + LN_EPS);
}

// ---------------- x_hat = LN0(x) materialized once ----------------------
__global__ void __launch_bounds__(256) k_ln0(const float* __restrict__ in,
                                             const float* __restrict__ w,
                                             const float* __restrict__ bb) {
    int b = blockIdx.x, c = blockIdx.y, tid = threadIdx.x;
    const int per = (NN * DI / 4) / SCH;   // 8192 float4
    float mean = g_mean[b], rstd = g_rstd[b];
    const float4* xin = (const float4*)(in + (size_t)b * NN * DI) + (size_t)c * per;
    const float4* w4  = (const float4*)w  + (size_t)c * per;
    const float4* b4  = (const float4*)bb + (size_t)c * per;
    float4* xo = (float4*)(g_xn + (size_t)b * NN * DI) + (size_t)c * per;
    for (int i = tid; i < per; i += 256) {
        float4 v = xin[i], ww = w4[i], bv = b4[i], o;
        o.x = (v.x - mean) * rstd * ww.x + bv.x;
        o.y = (v.y - mean) * rstd * ww.y + bv.y;
        o.z = (v.z - mean) * rstd * ww.z + bv.z;
        o.w = (v.w - mean) * rstd * ww.w + bv.w;
        xo[i] = o;
    }
}

// ---------------- slots = mu + exp(logsigma) * slots_init ---------------
__global__ void k_sinit(const float* __restrict__ si, const float* __restrict__ mu,
                        const float* __restrict__ ls) {
    int i = blockIdx.x * 256 + threadIdx.x;
    int d = i & (DO - 1);
    g_slots[i] = mu[d] + expf(ls[d]) * si[i];
}

// ---------------- Wqk = qW^T @ kW  (grid: 64 x TT) ----------------------
__global__ void __launch_bounds__(256) k_wqk(const float* __restrict__ qW,
                                             const float* __restrict__ qb,
                                             const float* __restrict__ kW,
                                             const float* __restrict__ kb) {
    int d0 = blockIdx.x * 4, t = blockIdx.y, i = threadIdx.x;
    int wid = i >> 5, lane = i & 31;
    __shared__ float qcols[DO * 4];
    __shared__ float kb_s[DO], qb_s[DO];
    {
        float4 v = *(const float4*)(qW + (size_t)t * DO * DO + (size_t)i * DO + d0);
        qcols[i * 4 + 0] = v.x; qcols[i * 4 + 1] = v.y;
        qcols[i * 4 + 2] = v.z; qcols[i * 4 + 3] = v.w;
        kb_s[i] = kb[t * DO + i];
        qb_s[i] = qb[t * DO + i];
    }
    __syncthreads();
    const float* kWt = kW + (size_t)t * DO * DI;
    float acc0 = 0.f, acc1 = 0.f, acc2 = 0.f, acc3 = 0.f, accq = 0.f;
#pragma unroll 8
    for (int e = 0; e < DO; e++) {
        float kv = kWt[(size_t)e * DI + i];
        acc0 += qcols[e * 4 + 0] * kv;
        acc1 += qcols[e * 4 + 1] * kv;
        acc2 += qcols[e * 4 + 2] * kv;
        acc3 += qcols[e * 4 + 3] * kv;
        accq += qb_s[e] * kv;
    }
    float* Wq = g_Wqk + (size_t)t * DO * DI;
    Wq[(d0 + 0) * DI + i] = acc0;
    Wq[(d0 + 1) * DI + i] = acc1;
    Wq[(d0 + 2) * DI + i] = acc2;
    Wq[(d0 + 3) * DI + i] = acc3;
    if (blockIdx.x == 0) g_wqb[t * DI + i] = accq;
    if (wid < 4) {
        float s = 0.f;
        for (int e = lane; e < DO; e += 32) s += qcols[e * 4 + wid] * kb_s[e];
#pragma unroll
        for (int o = 16; o > 0; o >>= 1) s += __shfl_xor_sync(0xffffffffu, s, o);
        if (lane == 0) g_wb[t * DO + d0 + wid] = s;
    }
    if (blockIdx.x == 0 && wid == 4) {
        float s = 0.f;
        for (int e = lane; e < DO; e += 32) s += qb_s[e] * kb_s[e];
#pragma unroll
        for (int o = 16; o > 0; o >>= 1) s += __shfl_xor_sync(0xffffffffu, s, o);
        if (lane == 0) g_c0[t] = s;
    }
}

// ---------------- LN1(slots) -> qk = sn @ Wqk + wqb  (grid: BB x 8) -----
// 2 slots per block (512 blocks: better latency hiding for the dot loops)
__global__ void __launch_bounds__(256) k_qk(const float* __restrict__ ln1w,
                                            const float* __restrict__ ln1b, int t) {
    int b = blockIdx.x, kh = blockIdx.y, tid = threadIdx.x;
    int wid = tid >> 5, lane = tid & 31;
    __shared__ float sl[KS * DO];
    __shared__ float ss[2 * DO];
    __shared__ float r1[256], r2[256];
    float s = 0.f, s2 = 0.f;
    for (int i = tid; i < KS * DO; i += 256) {
        float v = g_slots[b * KS * DO + i];
        sl[i] = v; s += v; s2 += v * v;
    }
    r1[tid] = s; r2[tid] = s2; __syncthreads();
    for (int o = 128; o > 0; o >>= 1) {
        if (tid < o) { r1[tid] += r1[tid + o]; r2[tid] += r2[tid + o]; }
        __syncthreads();
    }
    const float invC = 1.0f / (float)(KS * DO);
    float m = r1[0] * invC;
    float rs = rsqrtf(r2[0] * invC - m * m + LN_EPS);
    for (int i = tid; i < 2 * DO; i += 256) {
        int gi = kh * 2 * DO + i;
        ss[i] = (sl[gi] - m) * rs * ln1w[gi] + ln1b[gi];
    }
    __syncthreads();

    const float isc = 1.0f / (float)KS;
    const float* Wq = g_Wqk + (size_t)t * DO * DI;
    float acc0 = 0.f, acc1 = 0.f;
#pragma unroll 16
    for (int d = 0; d < DO; d++) {
        float wv = Wq[d * DI + tid];
        acc0 += ss[d] * wv;
        acc1 += ss[DO + d] * wv;
    }
    float wqbv = g_wqb[t * DI + tid];
    g_qk[b * KS * DI + (kh * 2 + 0) * DI + tid] = (acc0 + wqbv) * isc;
    g_qk[b * KS * DI + (kh * 2 + 1) * DI + tid] = (acc1 + wqbv) * isc;
    if (wid < 2) {
        float sb = 0.f;
        const float* wb = g_wb + t * DO;
        for (int d = lane; d < DO; d += 32) sb += ss[wid * DO + d] * wb[d];
#pragma unroll
        for (int o = 16; o > 0; o >>= 1) sb += __shfl_xor_sync(0xffffffffu, sb, o);
        if (lane == 0) g_qkb[b * KS + kh * 2 + wid] = (sb + g_c0[t]) * isc;
    }
}

// ---------------- big fused attention pass  (grid: BB x NCH) ------------
// LDS.128 loads, fused parallel softmax, occ 3, cp.async double buffering.
__global__ void __launch_bounds__(256, 3) k_attn() {
    int b = blockIdx.x, ch = blockIdx.y, tid = threadIdx.x;
    int kk = tid & 15, dg = tid >> 4;
    int wid = tid >> 5, lane = tid & 31;

    __shared__ float4 xs[2][16 * 64];    // double-buffered tiles, 32 KB (no pad: reads broadcast)
    __shared__ float  attn[KS][17];
    __shared__ float  red[8][16 * 17];
    __shared__ float  qkb_s[KS];

    // qk segment for (kk, dg): 16 floats as 8 float2 (already /KS scaled)
    const float2* qp = (const float2*)(g_qk + ((size_t)b * KS + kk) * DI + dg * 16);
    float2 q[8];
#pragma unroll
    for (int j = 0; j < 8; j++) q[j] = qp[j];
    if (tid < KS) qkb_s[tid] = g_qkb[b * KS + tid];

    float2 u[8];
#pragma unroll
    for (int j = 0; j < 8; j++) u[j] = make_float2(0.f, 0.f);
    float Sa = 0.f;

    const float4* xnb = (const float4*)(g_xn + ((size_t)b * NN + (size_t)ch * 128) * DI);

    // prefetch tile 0 (linear layout, stride 64 float4)
#pragma unroll
    for (int k = 0; k < 4; k++) {
        int i = tid + k * 256;
        cpasync16(&xs[0][i], &xnb[i]);
    }
    cp_commit();

    for (int g = 0; g < 8; g++) {
        const float4* buf = xs[g & 1];
        if (g < 7) {
            float4* nb = xs[(g + 1) & 1];
            const float4* src = xnb + (size_t)(g + 1) * 1024;
#pragma unroll
            for (int k = 0; k < 4; k++) {
                int i = tid + k * 256;
                cpasync16(&nb[i], &src[i]);
            }
            cp_commit();
            cp_wait<1>();
        } else {
            cp_wait<0>();
        }
        __syncthreads();

        // phase1: float4 partial dots; immediate shfl-fold + store (no p[] array)
#pragma unroll
        for (int n = 0; n < 16; n++) {
            const float4* xr = &buf[n * 64 + dg * 4];
            float2 acc = make_float2(0.f, 0.f);
#pragma unroll
            for (int j = 0; j < 4; j++) {
                float4 xv = xr[j];
                ffma2(acc, q[2 * j],     make_float2(xv.x, xv.y));
                ffma2(acc, q[2 * j + 1], make_float2(xv.z, xv.w));
            }
            float p = acc.x + acc.y;
            p += __shfl_xor_sync(0xffffffffu, p, 16);   // fold dg pair
            if (lane < 16) red[wid][lane * 17 + n] = p;
        }
        __syncthreads();

        // fused dist-assembly + softmax: thread (rkk = tid&15, rn = tid>>4).
        // All 16 slots of one n sit in a 16-lane half-warp -> shfl reductions.
        {
            int rkk = tid & 15, rn = tid >> 4;
            float s = qkb_s[rkk];
#pragma unroll
            for (int w = 0; w < 8; w++) s += red[w][rkk * 17 + rn];
            float mx = s;
#pragma unroll
            for (int o = 1; o < 16; o <<= 1)
                mx = fmaxf(mx, __shfl_xor_sync(0xffffffffu, mx, o));
            float e = __expf(s - mx);
            float sm = e;
#pragma unroll
            for (int o = 1; o < 16; o <<= 1)
                sm += __shfl_xor_sync(0xffffffffu, sm, o);
            attn[rkk][rn] = e * (1.0f / sm);
        }
        __syncthreads();

        if (tid < 16) {
#pragma unroll
            for (int n = 0; n < 16; n++) Sa += attn[tid][n];
        }

        // phase2: float4 x loads (broadcast), packed u accumulation
#pragma unroll
        for (int n = 0; n < 16; n++) {
            float w = attn[kk][n];
            float2 w2 = make_float2(w, w);
            const float4* xr = &buf[n * 64 + dg * 4];
#pragma unroll
            for (int j = 0; j < 4; j++) {
                float4 xv = xr[j];
                ffma2(u[2 * j],     w2, make_float2(xv.x, xv.y));
                ffma2(u[2 * j + 1], w2, make_float2(xv.z, xv.w));
            }
        }
        __syncthreads();   // all reads of buf done -> safe to prefetch into it
    }

    float4* up = (float4*)(g_upart + (((size_t)ch * BB + b) * KS + kk) * DI + dg * 16);
    up[0] = make_float4(u[0].x, u[0].y, u[1].x, u[1].y);
    up[1] = make_float4(u[2].x, u[2].y, u[3].x, u[3].y);
    up[2] = make_float4(u[4].x, u[4].y, u[5].x, u[5].y);
    up[3] = make_float4(u[6].x, u[6].y, u[7].x, u[7].y);
    if (tid < 16) g_Spart[(ch * BB + b) * KS + tid] = Sa;
}

// ---------------- reduce partials, V proj  (grid: BB x 4) ---------------
// 4 slots per block; one thread per (slot, float4-pos) in the reduce.
__global__ void __launch_bounds__(256) k_vproj(const float* __restrict__ vb, int t) {
    int b = blockIdx.x, kh = blockIdx.y, tid = threadIdx.x;
    __shared__ float wxs[4 * DI];
    __shared__ float wss[4], ivs[4];
    if (tid < 4) {
        float S = 0.f;
#pragma unroll 8
        for (int c = 0; c < NCH; c++) S += g_Spart[(c * BB + b) * KS + kh * 4 + tid];
        float iv = 1.0f / (S + 1e-7f);
        ivs[tid] = iv; wss[tid] = S * iv;
    }
    __syncthreads();
    {
        int k = tid >> 6, pos = tid & 63;   // 4 slots x 64 float4 = 256 threads
        const float4* src = (const float4*)g_upart +
            (((size_t)b * KS) + kh * 4 + k) * (DI / 4) + pos;
        float4 s = make_float4(0.f, 0.f, 0.f, 0.f);
#pragma unroll 8
        for (int c = 0; c < NCH; c++) {
            float4 v = src[(size_t)c * (BB * KS * DI / 4)];
            s.x += v.x; s.y += v.y; s.z += v.z; s.w += v.w;
        }
        float iv = ivs[k];
        s.x *= iv; s.y *= iv; s.z *= iv; s.w *= iv;
        ((float4*)wxs)[tid] = s;
    }
    __syncthreads();
    const float* vt = g_vWt + (size_t)t * DI * DO;
    float acc0 = 0.f, acc1 = 0.f, acc2 = 0.f, acc3 = 0.f;
#pragma unroll 8
    for (int d = 0; d < DI; d++) {
        float wv = vt[(size_t)d * DO + tid];
        acc0 += wxs[0 * DI + d] * wv;
        acc1 += wxs[1 * DI + d] * wv;
        acc2 += wxs[2 * DI + d] * wv;
        acc3 += wxs[3 * DI + d] * wv;
    }
    float vbv = vb[t * DO + tid];
    g_spre[b * KS * DO + (kh * 4 + 0) * DO + tid] = acc0 + vbv * wss[0];
    g_spre[b * KS * DO + (kh * 4 + 1) * DO + tid] = acc1 + vbv * wss[1];
    g_spre[b * KS * DO + (kh * 4 + 2) * DO + tid] = acc2 + vbv * wss[2];
    g_spre[b * KS * DO + (kh * 4 + 3) * DO + tid] = acc3 + vbv * wss[3];
}

// ---------------- LN2 + MLP + residual  (grid: BB x 8, 2 slots) ---------
__global__ void __launch_bounds__(256) k_mlp(const float* __restrict__ ln2w,
                                             const float* __restrict__ ln2b,
                                             const float* __restrict__ m1b,
                                             const float* __restrict__ m2b,
                                             int t, float* __restrict__ out) {
    int b = blockIdx.x, kq = blockIdx.y, tid = threadIdx.x;
    __shared__ float h0[2 * DO];
    __shared__ float hh[2 * HI];
    __shared__ float r1[256], r2[256];
    float s = 0.f, s2 = 0.f;
    for (int i = tid; i < KS * DO; i += 256) {
        float v = g_spre[b * KS * DO + i];
        s += v; s2 += v * v;
    }
    r1[tid] = s; r2[tid] = s2; __syncthreads();
    for (int o = 128; o > 0; o >>= 1) {
        if (tid < o) { r1[tid] += r1[tid + o]; r2[tid] += r2[tid + o]; }
        __syncthreads();
    }
    const float invC = 1.0f / (float)(KS * DO);
    float m = r1[0] * invC;
    float rs = rsqrtf(r2[0] * invC - m * m + LN_EPS);
    for (int i = tid; i < 2 * DO; i += 256) {
        int gi = kq * 2 * DO + i;
        float v = g_spre[b * KS * DO + gi];
        h0[i] = (v - m) * rs * ln2w[gi] + ln2b[gi];
    }
    __syncthreads();

    const float* w1 = g_m1Wt + (size_t)t * DO * HI;
    {
        float a00 = 0.f, a01 = 0.f, a10 = 0.f, a11 = 0.f;
#pragma unroll 8
        for (int d = 0; d < DO; d++) {
            float wA = w1[(size_t)d * HI + tid];
            float wB = w1[(size_t)d * HI + tid + 256];
            float h0v = h0[d], h1v = h0[DO + d];
            a00 += h0v * wA; a01 += h0v * wB;
            a10 += h1v * wA; a11 += h1v * wB;
        }
        float bA = m1b[t * HI + tid], bB = m1b[t * HI + tid + 256];
        hh[0 * HI + tid]       = fmaxf(a00 + bA, 0.f);
        hh[0 * HI + tid + 256] = fmaxf(a01 + bB, 0.f);
        hh[1 * HI + tid]       = fmaxf(a10 + bA, 0.f);
        hh[1 * HI + tid + 256] = fmaxf(a11 + bB, 0.f);
    }
    __syncthreads();

    const float* w2 = g_m2Wt + (size_t)t * HI * DO;
    float a0 = 0.f, a1 = 0.f;
#pragma unroll 8
    for (int h = 0; h < HI; h++) {
        float wv = w2[(size_t)h * DO + tid];
        a0 += hh[h] * wv;
        a1 += hh[HI + h] * wv;
    }
    float b2 = m2b[t * DO + tid];
    {
        int gi0 = (kq * 2 + 0) * DO + tid;
        int gi1 = (kq * 2 + 1) * DO + tid;
        float v0 = g_spre[b * KS * DO + gi0] + a0 + b2;
        float v1 = g_spre[b * KS * DO + gi1] + a1 + b2;
        g_slots[b * KS * DO + gi0] = v0;
        g_slots[b * KS * DO + gi1] = v1;
        if (out) {
            out[(size_t)b * KS * DO + gi0] = v0;
            out[(size_t)b * KS * DO + gi1] = v1;
        }
    }
}

// ---------------- host launcher -----------------------------------------
extern "C" void kernel_launch(void* const* d_in, const int* in_sizes, int n_in,
                              void* d_out, int out_size) {
    const float* inputs     = (const float*)d_in[0];
    const float* slots_init = (const float*)d_in[1];
    const float* mu         = (const float*)d_in[2];
    const float* logsigma   = (const float*)d_in[3];
    const float* ln0w       = (const float*)d_in[4];
    const float* ln0b       = (const float*)d_in[5];
    const float* ln1w       = (const float*)d_in[6];
    const float* ln1b       = (const float*)d_in[7];
    const float* ln2w       = (const float*)d_in[8];
    const float* ln2b       = (const float*)d_in[9];
    const float* qW         = (const float*)d_in[10];
    const float* qb         = (const float*)d_in[11];
    const float* kW         = (const float*)d_in[12];
    const float* kb         = (const float*)d_in[13];
    const float* vW         = (const float*)d_in[14];
    const float* vb         = (const float*)d_in[15];
    const float* m1W        = (const float*)d_in[16];
    const float* m1b        = (const float*)d_in[17];
    const float* m2W        = (const float*)d_in[18];
    const float* m2b        = (const float*)d_in[19];
    float* out = (float*)d_out;

    float* vWt;  cudaGetSymbolAddress((void**)&vWt,  g_vWt);
    float* m1Wt; cudaGetSymbolAddress((void**)&m1Wt, g_m1Wt);
    float* m2Wt; cudaGetSymbolAddress((void**)&m2Wt, g_m2Wt);
    k_tr<<<dim3(DI / 32, DO / 32, TT), 256>>>(vW, vWt, DO, DI);
    k_tr<<<dim3(DO / 32, HI / 32, TT), 256>>>(m1W, m1Wt, HI, DO);
    k_tr<<<dim3(HI / 32, DO / 32, TT), 256>>>(m2W, m2Wt, DO, HI);

    // PROFILING PROBE: 1-block k_attn at ncu's capture slot (#4).
    // Reads stale/zero g_qk (finite); its g_upart/g_Spart writes are fully
    // overwritten by the real k_attn launches below -> output unaffected.
    k_attn<<<dim3(1, 1), 256>>>();

    k_wqk<<<dim3(64, TT), 256>>>(qW, qb, kW, kb);   // all iterations up front
    k_stats<<<dim3(BB, SCH), 256>>>(inputs);
    k_fin<<<1, BB>>>();
    k_ln0<<<dim3(BB, SCH), 256>>>(inputs, ln0w, ln0b);
    k_sinit<<<(BB * KS * DO) / 256, 256>>>(slots_init, mu, logsigma);

    for (int t = 0; t < TT; t++) {
        k_qk<<<dim3(BB, 8), 256>>>(ln1w, ln1b, t);
        k_attn<<<dim3(BB, NCH), 256>>>();
        k_vproj<<<dim3(BB, 4), 256>>>(vb, t);
        k_mlp<<<dim3(BB, 8), 256>>>(ln2w, ln2b, m1b, m2b, t,
                                    (t == TT - 1) ? out : (float*)nullptr);
    }
}